// round 2
// baseline (speedup 1.0000x reference)
#include <cuda_runtime.h>
#include <cuda_bf16.h>

#define N_NODES 50000
#define N_EDGES 800000
#define KPTS 15
#define IN_DIM 32
#define OUT_DIM 64
#define KI (KPTS * IN_DIM)   // 480
#define KP_EXT 0.6f

// 96 MB scratch for segment-summed weighted features [N_NODES, K*IN].
// Zero-initialized at module load; the GEMM kernel re-zeroes every element it
// consumes, so the zero-invariant holds across graph replays.
__device__ float g_wf[(size_t)N_NODES * KI];

// One warp per edge. Lane i owns input-feature channel i.
// Lanes 0..14 compute the influence m[k]; ballot skips edges/kernel-points
// with zero influence (the common case given the geometry).
__global__ void edge_scatter(const float* __restrict__ pos,
                             const float* __restrict__ feat,
                             const float* __restrict__ kp,
                             const int*   __restrict__ esrc,
                             const int*   __restrict__ edst) {
    int e = blockIdx.x * 8 + (threadIdx.x >> 5);
    if (e >= N_EDGES) return;
    int lane = threadIdx.x & 31;

    int src = __ldg(esrc + e);
    int dst = __ldg(edst + e);

    float y0 = __ldg(pos + src * 3 + 0) - __ldg(pos + dst * 3 + 0);
    float y1 = __ldg(pos + src * 3 + 1) - __ldg(pos + dst * 3 + 1);
    float y2 = __ldg(pos + src * 3 + 2) - __ldg(pos + dst * 3 + 2);

    float m = 0.f;
    if (lane < KPTS) {
        float d0 = y0 - __ldg(kp + lane * 3 + 0);
        float d1 = y1 - __ldg(kp + lane * 3 + 1);
        float d2 = y2 - __ldg(kp + lane * 3 + 2);
        float dist = sqrtf(d0 * d0 + d1 * d1 + d2 * d2);
        m = fmaxf(0.f, 1.f - dist * (1.f / KP_EXT));
    }

    unsigned nz = __ballot_sync(0xffffffffu, m > 0.f);
    if (!nz) return;  // warp-uniform

    float f = __ldg(feat + (size_t)src * IN_DIM + lane);
    float* base = g_wf + (size_t)dst * KI + lane;

    while (nz) {
        int k = __ffs(nz) - 1;
        nz &= nz - 1;
        float mk = __shfl_sync(0xffffffffu, m, k);
        atomicAdd(base + k * 32, mk * f);  // 32-lane coalesced
    }
}

// C[64-row tile, 64 cols] = wf_tile @ W.  256 threads, 4x4 micro-tile each.
// Re-zeroes wf as it reads (each element touched by exactly one block once).
#define TROWS 64
#define KT 32

__global__ void node_gemm(const float* __restrict__ W, float* __restrict__ out) {
    __shared__ float As[TROWS][KT + 1];
    __shared__ float Bs[KT][OUT_DIM];

    int tid = threadIdx.x;           // 0..255
    int rowBase = blockIdx.x * TROWS;
    int tx = tid & 15;               // output-col group (4 cols)
    int ty = tid >> 4;               // output-row group (4 rows)

    float acc[4][4] = {};

    for (int kt = 0; kt < KI; kt += KT) {
        // Load A tile (64x32) coalesced; zero the source behind us.
        #pragma unroll
        for (int j = 0; j < 8; j++) {
            int idx = j * 256 + tid;
            int r = idx >> 5, kk = idx & 31;
            int row = rowBase + r;
            float v = 0.f;
            if (row < N_NODES) {
                size_t g = (size_t)row * KI + kt + kk;
                v = g_wf[g];
                g_wf[g] = 0.f;
            }
            As[r][kk] = v;
        }
        // Load B tile (32x64) coalesced.
        #pragma unroll
        for (int j = 0; j < 8; j++) {
            int idx = j * 256 + tid;
            int kk = idx >> 6, c = idx & 63;
            Bs[kk][c] = __ldg(W + (size_t)(kt + kk) * OUT_DIM + c);
        }
        __syncthreads();

        #pragma unroll
        for (int kk = 0; kk < KT; kk++) {
            float4 b = *(const float4*)&Bs[kk][tx * 4];
            #pragma unroll
            for (int i = 0; i < 4; i++) {
                float a = As[ty * 4 + i][kk];
                acc[i][0] = fmaf(a, b.x, acc[i][0]);
                acc[i][1] = fmaf(a, b.y, acc[i][1]);
                acc[i][2] = fmaf(a, b.z, acc[i][2]);
                acc[i][3] = fmaf(a, b.w, acc[i][3]);
            }
        }
        __syncthreads();
    }

    #pragma unroll
    for (int i = 0; i < 4; i++) {
        int row = rowBase + ty * 4 + i;
        if (row < N_NODES) {
            float4 v = make_float4(acc[i][0], acc[i][1], acc[i][2], acc[i][3]);
            *(float4*)(out + (size_t)row * OUT_DIM + tx * 4) = v;
        }
    }
}

extern "C" void kernel_launch(void* const* d_in, const int* in_sizes, int n_in,
                              void* d_out, int out_size) {
    const float* pos  = (const float*)d_in[0];
    const float* feat = (const float*)d_in[1];
    const float* kp   = (const float*)d_in[2];
    const float* W    = (const float*)d_in[3];
    const int*   esrc = (const int*)d_in[4];
    const int*   edst = (const int*)d_in[5];
    float* out = (float*)d_out;

    edge_scatter<<<(N_EDGES + 7) / 8, 256>>>(pos, feat, kp, esrc, edst);
    node_gemm<<<(N_NODES + TROWS - 1) / TROWS, 256>>>(W, out);
}

// round 3
// speedup vs baseline: 6.3574x; 6.3574x over previous
#include <cuda_runtime.h>
#include <cuda_bf16.h>

#define N_NODES 50000
#define N_EDGES 800000
#define KPTS 15
#define IN_DIM 32
#define OUT_DIM 64
#define KI (KPTS * IN_DIM)   // 480
#define KP_EXT 0.6f

// 96 MB scratch for segment-summed weighted features [N_NODES, K*IN].
// Zero-initialized at module load; node_gemm's epilogue re-zeroes every row it
// consumed, so the zero-invariant holds across graph replays.
__device__ float g_wf[(size_t)N_NODES * KI];

// ---------------------------------------------------------------------------
// Edge phase: one warp per edge. Lane i owns input channel i.
// Lanes 0..14 compute influence m[k]; ballot skips fully-zero edges (common).
// ---------------------------------------------------------------------------
__global__ void edge_scatter(const float* __restrict__ pos,
                             const float* __restrict__ feat,
                             const float* __restrict__ kp,
                             const int*   __restrict__ esrc,
                             const int*   __restrict__ edst) {
    int e = blockIdx.x * 8 + (threadIdx.x >> 5);
    if (e >= N_EDGES) return;
    int lane = threadIdx.x & 31;

    int src = __ldg(esrc + e);
    int dst = __ldg(edst + e);

    float y0 = __ldg(pos + src * 3 + 0) - __ldg(pos + dst * 3 + 0);
    float y1 = __ldg(pos + src * 3 + 1) - __ldg(pos + dst * 3 + 1);
    float y2 = __ldg(pos + src * 3 + 2) - __ldg(pos + dst * 3 + 2);

    float m = 0.f;
    if (lane < KPTS) {
        float d0 = y0 - __ldg(kp + lane * 3 + 0);
        float d1 = y1 - __ldg(kp + lane * 3 + 1);
        float d2 = y2 - __ldg(kp + lane * 3 + 2);
        float dist = sqrtf(d0 * d0 + d1 * d1 + d2 * d2);
        m = fmaxf(0.f, 1.f - dist * (1.f / KP_EXT));
    }

    unsigned nz = __ballot_sync(0xffffffffu, m > 0.f);
    if (!nz) return;  // warp-uniform

    float f = __ldg(feat + (size_t)src * IN_DIM + lane);
    float* base = g_wf + (size_t)dst * KI + lane;

    while (nz) {
        int k = __ffs(nz) - 1;
        nz &= nz - 1;
        float mk = __shfl_sync(0xffffffffu, m, k);
        atomicAdd(base + k * 32, mk * f);  // 32-lane coalesced
    }
}

// ---------------------------------------------------------------------------
// Node phase: out[128-row tile, 64] = wf_tile[128,480] @ W[480,64].
// 256 threads; each thread owns 8 rows x 4 cols, accumulated as packed f32x2
// row-pairs (full-rate FFMA2 path on sm_103a). Register-staged double
// buffering: next tile's global loads are issued as a pure LDG batch while the
// current tile computes. A is stored transposed in smem so row-pairs are
// contiguous 8B LDS.64. Epilogue zero-fills this block's g_wf rows with pure
// coalesced stores (replay invariant; no other block reads these rows).
// ---------------------------------------------------------------------------
#define TROWS 128
#define TCOLS 64
#define KT 32
#define A_STRIDE (TROWS + 2)   // even stride: keeps 8B alignment, mild conflicts
#define B_STRIDE (TCOLS + 4)

__global__ __launch_bounds__(256) void node_gemm(const float* __restrict__ W,
                                                 float* __restrict__ out) {
    __shared__ float As[KT][A_STRIDE];   // transposed: As[kk][row]
    __shared__ float Bs[KT][B_STRIDE];

    const int tid = threadIdx.x;
    const int rowBase = blockIdx.x * TROWS;
    const int tx = tid & 15;   // col group: cols tx*4 .. tx*4+3
    const int ty = tid >> 4;   // row group: rows ty*8 .. ty*8+7

    // A-load mapping: thread loads 4x float4 per tile:
    //   row = rowBase + (tid>>3) + 32*j,  cols kt + (tid&7)*4 .. +3
    const int lr  = tid >> 3;
    const int lk4 = tid & 7;

    unsigned long long acc[4][4];   // [row-pair][col], packed f32x2
    #pragma unroll
    for (int p = 0; p < 4; p++)
        #pragma unroll
        for (int c = 0; c < 4; c++) acc[p][c] = 0ull;

    float4 aReg[4];
    float4 bReg[2];

    // ---- prologue: batched global loads of tile 0 (pure LDG, MLP=6) ----
    #pragma unroll
    for (int j = 0; j < 4; j++) {
        int row = rowBase + lr + 32 * j;
        aReg[j] = (row < N_NODES)
            ? *(const float4*)(g_wf + (size_t)row * KI + lk4 * 4)
            : make_float4(0.f, 0.f, 0.f, 0.f);
    }
    #pragma unroll
    for (int q = 0; q < 2; q++) {
        int idx = q * 256 + tid;           // 0..511 over 32x16 float4s
        int kk = idx >> 4, c4 = idx & 15;
        bReg[q] = *(const float4*)(W + (size_t)kk * OUT_DIM + c4 * 4);
    }

    for (int kt = 0; kt < KI; kt += KT) {
        // ---- stage regs -> smem (A transposed) ----
        #pragma unroll
        for (int j = 0; j < 4; j++) {
            int r = lr + 32 * j;
            As[lk4 * 4 + 0][r] = aReg[j].x;
            As[lk4 * 4 + 1][r] = aReg[j].y;
            As[lk4 * 4 + 2][r] = aReg[j].z;
            As[lk4 * 4 + 3][r] = aReg[j].w;
        }
        #pragma unroll
        for (int q = 0; q < 2; q++) {
            int idx = q * 256 + tid;
            int kk = idx >> 4, c4 = idx & 15;
            *(float4*)&Bs[kk][c4 * 4] = bReg[q];
        }
        __syncthreads();

        // ---- issue next tile's global loads (batched, no deps on compute) --
        if (kt + KT < KI) {
            #pragma unroll
            for (int j = 0; j < 4; j++) {
                int row = rowBase + lr + 32 * j;
                aReg[j] = (row < N_NODES)
                    ? *(const float4*)(g_wf + (size_t)row * KI + kt + KT + lk4 * 4)
                    : make_float4(0.f, 0.f, 0.f, 0.f);
            }
            #pragma unroll
            for (int q = 0; q < 2; q++) {
                int idx = q * 256 + tid;
                int kk = idx >> 4, c4 = idx & 15;
                bReg[q] = *(const float4*)(W + (size_t)(kt + KT + kk) * OUT_DIM + c4 * 4);
            }
        }

        // ---- compute: 16 FFMA2 per k per thread ----
        #pragma unroll
        for (int kk = 0; kk < KT; kk++) {
            unsigned long long ap[4];
            #pragma unroll
            for (int p = 0; p < 4; p++)
                ap[p] = *(const unsigned long long*)&As[kk][ty * 8 + 2 * p];

            float4 bv = *(const float4*)&Bs[kk][tx * 4];
            unsigned long long bb[4];
            asm("mov.b64 %0, {%1,%1};" : "=l"(bb[0]) : "r"(__float_as_uint(bv.x)));
            asm("mov.b64 %0, {%1,%1};" : "=l"(bb[1]) : "r"(__float_as_uint(bv.y)));
            asm("mov.b64 %0, {%1,%1};" : "=l"(bb[2]) : "r"(__float_as_uint(bv.z)));
            asm("mov.b64 %0, {%1,%1};" : "=l"(bb[3]) : "r"(__float_as_uint(bv.w)));

            #pragma unroll
            for (int p = 0; p < 4; p++)
                #pragma unroll
                for (int c = 0; c < 4; c++)
                    asm("fma.rn.f32x2 %0, %1, %2, %0;"
                        : "+l"(acc[p][c]) : "l"(ap[p]), "l"(bb[c]));
        }
        __syncthreads();
    }

    // ---- epilogue: write output ----
    #pragma unroll
    for (int p = 0; p < 4; p++) {
        unsigned lo0, hi0, lo1, hi1, lo2, hi2, lo3, hi3;
        asm("mov.b64 {%0,%1}, %2;" : "=r"(lo0), "=r"(hi0) : "l"(acc[p][0]));
        asm("mov.b64 {%0,%1}, %2;" : "=r"(lo1), "=r"(hi1) : "l"(acc[p][1]));
        asm("mov.b64 {%0,%1}, %2;" : "=r"(lo2), "=r"(hi2) : "l"(acc[p][2]));
        asm("mov.b64 {%0,%1}, %2;" : "=r"(lo3), "=r"(hi3) : "l"(acc[p][3]));
        int row0 = rowBase + ty * 8 + 2 * p;
        int row1 = row0 + 1;
        if (row0 < N_NODES)
            *(float4*)(out + (size_t)row0 * OUT_DIM + tx * 4) =
                make_float4(__uint_as_float(lo0), __uint_as_float(lo1),
                            __uint_as_float(lo2), __uint_as_float(lo3));
        if (row1 < N_NODES)
            *(float4*)(out + (size_t)row1 * OUT_DIM + tx * 4) =
                make_float4(__uint_as_float(hi0), __uint_as_float(hi1),
                            __uint_as_float(hi2), __uint_as_float(hi3));
    }

    // ---- epilogue: re-zero this block's g_wf rows (pure coalesced stores) --
    const int ZTOT = TROWS * (KI / 4);   // float4 count = 15360
    for (int idx = tid; idx < ZTOT; idx += 256) {
        int r = idx / (KI / 4);
        int c4 = idx - r * (KI / 4);
        int row = rowBase + r;
        if (row < N_NODES)
            *(float4*)(g_wf + (size_t)row * KI + c4 * 4) =
                make_float4(0.f, 0.f, 0.f, 0.f);
    }
}

extern "C" void kernel_launch(void* const* d_in, const int* in_sizes, int n_in,
                              void* d_out, int out_size) {
    const float* pos  = (const float*)d_in[0];
    const float* feat = (const float*)d_in[1];
    const float* kp   = (const float*)d_in[2];
    const float* W    = (const float*)d_in[3];
    const int*   esrc = (const int*)d_in[4];
    const int*   edst = (const int*)d_in[5];
    float* out = (float*)d_out;

    edge_scatter<<<(N_EDGES + 7) / 8, 256>>>(pos, feat, kp, esrc, edst);
    node_gemm<<<(N_NODES + TROWS - 1) / TROWS, 256>>>(W, out);
}

// round 5
// speedup vs baseline: 20.8412x; 3.2783x over previous
#include <cuda_runtime.h>
#include <cuda_bf16.h>

#define N_NODES 50000
#define N_EDGES 800000
#define KPTS 15
#define IN_DIM 32
#define OUT_DIM 64
#define KP_EXT 0.6f
#define BIN_CAP 131072          // per-k pair capacity (~8x expected max)
#define PB_BLOCKS_PER_K 48
#define PB_GRID (KPTS * PB_BLOCKS_PER_K)

// Sparse pair bins: per kernel-point k, list of {src, dst, m}.
__device__ float4 g_pos4[N_NODES];                       // 0.8 MB
__device__ float4 g_pairs[(size_t)KPTS * BIN_CAP];       // 31.5 MB
__device__ int    g_cnt[KPTS];

// ---------------------------------------------------------------------------
// Prep: zero output (poisoned by harness), pack pos to float4, reset counters.
// ---------------------------------------------------------------------------
__global__ __launch_bounds__(256) void k_prep(const float* __restrict__ pos,
                                              float* __restrict__ out, int out4) {
    int i = blockIdx.x * 256 + threadIdx.x;
    if (i < KPTS) g_cnt[i] = 0;
    if (i < N_NODES)
        g_pos4[i] = make_float4(__ldg(pos + 3 * i), __ldg(pos + 3 * i + 1),
                                __ldg(pos + 3 * i + 2), 0.f);
    if (i < out4) ((float4*)out)[i] = make_float4(0.f, 0.f, 0.f, 0.f);
}

// ---------------------------------------------------------------------------
// Geometry: thread per edge. Ball test per kernel point (d^2 compare, no
// sqrt). Active (e,k) pairs binned by k: block-local smem counts -> one
// global atomicAdd per k per block -> scatter entries.
// ---------------------------------------------------------------------------
__global__ __launch_bounds__(256) void k_geom(const float* __restrict__ kp,
                                              const int* __restrict__ esrc,
                                              const int* __restrict__ edst) {
    __shared__ float skp[KPTS * 3];
    __shared__ int scnt[KPTS], sbase[KPTS];
    int tid = threadIdx.x;
    if (tid < KPTS * 3) skp[tid] = __ldg(kp + tid);
    if (tid < KPTS) scnt[tid] = 0;
    __syncthreads();

    int e = blockIdx.x * 256 + tid;
    unsigned mask = 0;
    int src = 0, dst = 0;
    float y0 = 0.f, y1 = 0.f, y2 = 0.f;
    if (e < N_EDGES) {
        src = __ldg(esrc + e);
        dst = __ldg(edst + e);
        float4 ps = g_pos4[src], pd = g_pos4[dst];
        y0 = ps.x - pd.x; y1 = ps.y - pd.y; y2 = ps.z - pd.z;
        #pragma unroll
        for (int k = 0; k < KPTS; k++) {
            float d0 = y0 - skp[3 * k], d1 = y1 - skp[3 * k + 1], d2 = y2 - skp[3 * k + 2];
            if (d0 * d0 + d1 * d1 + d2 * d2 < KP_EXT * KP_EXT) mask |= (1u << k);
        }
    }

    unsigned mm = mask;
    while (mm) { int k = __ffs(mm) - 1; mm &= mm - 1; atomicAdd(&scnt[k], 1); }
    __syncthreads();
    if (tid < KPTS) { sbase[tid] = atomicAdd(&g_cnt[tid], scnt[tid]); scnt[tid] = 0; }
    __syncthreads();

    mm = mask;
    while (mm) {
        int k = __ffs(mm) - 1; mm &= mm - 1;
        int slot = sbase[k] + atomicAdd(&scnt[k], 1);
        if (slot < BIN_CAP) {
            float d0 = y0 - skp[3 * k], d1 = y1 - skp[3 * k + 1], d2 = y2 - skp[3 * k + 2];
            float m = 1.f - sqrtf(d0 * d0 + d1 * d1 + d2 * d2) * (1.f / KP_EXT);
            if (m < 0.f) m = 0.f;
            g_pairs[(size_t)k * BIN_CAP + slot] =
                make_float4(__int_as_float(src), __int_as_float(dst), m, 0.f);
        }
    }
}

// ---------------------------------------------------------------------------
// Apply: block group per kernel point. W_k (8KB) staged in smem once, reused
// across the whole bin. Warp processes 4 pairs per pass (W amortized 4x).
// Lane = h*16 + c4: owns cols 4*c4..4*c4+3, sums i-half h; halves combined by
// shfl_xor(16); h==0 lanes emit one red.global.add.v4.f32 per pair.
// All intra-loop branches are warp-uniform (cnt, dsts broadcast) -> no hangs.
// ---------------------------------------------------------------------------
__global__ __launch_bounds__(256) void k_apply(const float* __restrict__ W,
                                               const float* __restrict__ feat,
                                               float* __restrict__ out) {
    __shared__ __align__(16) float4 sW[IN_DIM * 16];   // [i][c4] : 8 KB
    __shared__ __align__(16) float  sF[8][IN_DIM][4];  // [warp][i][pair] : 4 KB

    int k = blockIdx.x / PB_BLOCKS_PER_K;
    int blkInK = blockIdx.x - k * PB_BLOCKS_PER_K;
    int tid = threadIdx.x;

    const float4* Wk = (const float4*)(W + (size_t)k * IN_DIM * OUT_DIM);
    sW[tid]       = __ldg(Wk + tid);
    sW[tid + 256] = __ldg(Wk + tid + 256);
    __syncthreads();

    int cnt = g_cnt[k];
    cnt = (cnt < BIN_CAP) ? cnt : BIN_CAP;
    if (cnt <= 0) return;
    int lane = tid & 31, wl = tid >> 5;
    int h = lane >> 4, c4 = lane & 15;
    const float4* bin = g_pairs + (size_t)k * BIN_CAP;
    int wik = blkInK * 8 + wl;

    for (int base = wik * 4; base < cnt; base += PB_BLOCKS_PER_K * 8 * 4) {
        int nv = cnt - base; if (nv > 4) nv = 4;
        int dsts[4];
        float fh[4];
        #pragma unroll
        for (int p = 0; p < 4; p++) {
            if (p < nv) {
                float4 ent = __ldg(bin + base + p);       // broadcast
                int sp = __float_as_int(ent.x);
                dsts[p] = __float_as_int(ent.y);
                fh[p] = __ldg(feat + (size_t)sp * IN_DIM + lane) * ent.z;  // m*f_i
            } else { dsts[p] = -1; fh[p] = 0.f; }
        }
        *(float4*)&sF[wl][lane][0] = make_float4(fh[0], fh[1], fh[2], fh[3]);
        __syncwarp();

        unsigned long long a01[4] = {0,0,0,0}, a23[4] = {0,0,0,0};
        #pragma unroll
        for (int s = 0; s < 16; s++) {
            int i = s + 16 * h;
            float4 w = sW[i * 16 + c4];
            unsigned long long w01, w23;
            asm("mov.b64 %0, {%1,%2};" : "=l"(w01)
                : "r"(__float_as_uint(w.x)), "r"(__float_as_uint(w.y)));
            asm("mov.b64 %0, {%1,%2};" : "=l"(w23)
                : "r"(__float_as_uint(w.z)), "r"(__float_as_uint(w.w)));
            float4 f4 = *(const float4*)&sF[wl][i][0];
            unsigned long long fp0, fp1, fp2, fp3;
            asm("mov.b64 %0, {%1,%1};" : "=l"(fp0) : "r"(__float_as_uint(f4.x)));
            asm("mov.b64 %0, {%1,%1};" : "=l"(fp1) : "r"(__float_as_uint(f4.y)));
            asm("mov.b64 %0, {%1,%1};" : "=l"(fp2) : "r"(__float_as_uint(f4.z)));
            asm("mov.b64 %0, {%1,%1};" : "=l"(fp3) : "r"(__float_as_uint(f4.w)));
            asm("fma.rn.f32x2 %0, %1, %2, %0;" : "+l"(a01[0]) : "l"(fp0), "l"(w01));
            asm("fma.rn.f32x2 %0, %1, %2, %0;" : "+l"(a23[0]) : "l"(fp0), "l"(w23));
            asm("fma.rn.f32x2 %0, %1, %2, %0;" : "+l"(a01[1]) : "l"(fp1), "l"(w01));
            asm("fma.rn.f32x2 %0, %1, %2, %0;" : "+l"(a23[1]) : "l"(fp1), "l"(w23));
            asm("fma.rn.f32x2 %0, %1, %2, %0;" : "+l"(a01[2]) : "l"(fp2), "l"(w01));
            asm("fma.rn.f32x2 %0, %1, %2, %0;" : "+l"(a23[2]) : "l"(fp2), "l"(w23));
            asm("fma.rn.f32x2 %0, %1, %2, %0;" : "+l"(a01[3]) : "l"(fp3), "l"(w01));
            asm("fma.rn.f32x2 %0, %1, %2, %0;" : "+l"(a23[3]) : "l"(fp3), "l"(w23));
        }
        __syncwarp();

        #pragma unroll
        for (int p = 0; p < 4; p++) {
            if (dsts[p] < 0) continue;   // warp-uniform (broadcast value)
            unsigned x0, x1, x2, x3;
            asm("mov.b64 {%0,%1}, %2;" : "=r"(x0), "=r"(x1) : "l"(a01[p]));
            asm("mov.b64 {%0,%1}, %2;" : "=r"(x2), "=r"(x3) : "l"(a23[p]));
            float v0 = __uint_as_float(x0), v1 = __uint_as_float(x1);
            float v2 = __uint_as_float(x2), v3 = __uint_as_float(x3);
            v0 += __shfl_xor_sync(0xffffffffu, v0, 16);
            v1 += __shfl_xor_sync(0xffffffffu, v1, 16);
            v2 += __shfl_xor_sync(0xffffffffu, v2, 16);
            v3 += __shfl_xor_sync(0xffffffffu, v3, 16);
            if (h == 0) {
                float* dp = out + (size_t)dsts[p] * OUT_DIM + c4 * 4;
                asm volatile("red.global.add.v4.f32 [%0], {%1,%2,%3,%4};"
                             :: "l"(dp), "f"(v0), "f"(v1), "f"(v2), "f"(v3)
                             : "memory");
            }
        }
    }
}

extern "C" void kernel_launch(void* const* d_in, const int* in_sizes, int n_in,
                              void* d_out, int out_size) {
    const float* pos  = (const float*)d_in[0];
    const float* feat = (const float*)d_in[1];
    const float* kp   = (const float*)d_in[2];
    const float* W    = (const float*)d_in[3];
    const int*   esrc = (const int*)d_in[4];
    const int*   edst = (const int*)d_in[5];
    float* out = (float*)d_out;

    int out4 = out_size >> 2;                      // float4 count
    int prepBlocks = (out4 + 255) / 256;           // also covers N_NODES, KPTS
    k_prep<<<prepBlocks, 256>>>(pos, out, out4);
    k_geom<<<(N_EDGES + 255) / 256, 256>>>(kp, esrc, edst);
    k_apply<<<PB_GRID, 256>>>(W, feat, out);
}